// round 5
// baseline (speedup 1.0000x reference)
#include <cuda_runtime.h>
#include <cuda_fp16.h>

#define NN 100000
#define NE 1600000
#define F_IN 128
#define F_HID 128
#define F_CLS 64
#define NBLK_SCAN 98            // ceil(NN/1024)
#define GB1 ((NN + 63) / 64)    // 64-row tile blocks = 1563
#define FILL_BLOCKS 1024

// ---- scratch (device globals; no allocs allowed) ----
__device__ int    g_cnt_in[NN];
__device__ int    g_cnt_out[NN];
__device__ int    g_row_ptr[NN + 1];
__device__ int    g_cursor[NN];
__device__ int    g_csr_src[NE];
__device__ float  g_norm_in[NN];
__device__ float  g_norm_out[NN];
__device__ int    g_bsum[NBLK_SCAN + 1];
__device__ __half g_t1[(size_t)NN * F_HID];   // fp16 intermediate (layer1 post-GEMM)
__device__ __half g_t2[(size_t)NN * F_CLS];   // fp16 intermediate (layer2 post-GEMM)

// ---- fp16 vector load helpers (via uint __ldg overloads) ----
__device__ __forceinline__ void ldg_h4_f(const __half* p, float2& lo, float2& hi) {
    uint2 raw = __ldg((const uint2*)p);
    lo = __half22float2(*(const __half2*)&raw.x);
    hi = __half22float2(*(const __half2*)&raw.y);
}
__device__ __forceinline__ float2 ldg_h2_f(const __half* p) {
    unsigned int raw = __ldg((const unsigned int*)p);
    return __half22float2(*(const __half2*)&raw);
}

struct alignas(8) half4 { __half2 a, b; };

// ---- f32x2 packed-math helpers (sm_10x) ----
__device__ __forceinline__ unsigned long long fma2(unsigned long long a,
                                                   unsigned long long b,
                                                   unsigned long long c) {
    unsigned long long d;
    asm("fma.rn.f32x2 %0, %1, %2, %3;" : "=l"(d) : "l"(a), "l"(b), "l"(c));
    return d;
}
__device__ __forceinline__ unsigned long long dup2(float x) {
    unsigned long long d;
    unsigned int xb = __float_as_uint(x);
    asm("mov.b64 %0, {%1, %1};" : "=l"(d) : "r"(xb));
    return d;
}
__device__ __forceinline__ float2 unpk(unsigned long long v) {
    unsigned int lo, hi;
    asm("mov.b64 {%0, %1}, %2;" : "=r"(lo), "=r"(hi) : "l"(v));
    return make_float2(__uint_as_float(lo), __uint_as_float(hi));
}

__device__ __forceinline__ int warp_incl_scan(int x, int lane) {
#pragma unroll
    for (int o = 1; o < 32; o <<= 1) {
        int y = __shfl_up_sync(0xffffffffu, x, o);
        if (lane >= o) x += y;
    }
    return x;
}

// ===========================================================================
// CSR build
// ===========================================================================
__global__ void zero_counts() {
    int stride = gridDim.x * blockDim.x;
    for (int i = blockIdx.x * blockDim.x + threadIdx.x; i < NN; i += stride) {
        g_cnt_in[i] = 0; g_cnt_out[i] = 0;
    }
}

__global__ void count_kernel(const int* __restrict__ src,
                             const int* __restrict__ dst) {
    int e = blockIdx.x * blockDim.x + threadIdx.x;
    if (e < NE) {
        atomicAdd(&g_cnt_out[src[e]], 1);
        atomicAdd(&g_cnt_in[dst[e]], 1);
    }
}

__global__ __launch_bounds__(1024) void block_reduce_kernel() {
    __shared__ int ws[32];
    int t = threadIdx.x, lane = t & 31, wid = t >> 5;
    int i = blockIdx.x * 1024 + t;
    int v = (i < NN) ? g_cnt_in[i] : 0;
    int s = __reduce_add_sync(0xffffffffu, v);
    if (lane == 0) ws[wid] = s;
    __syncthreads();
    if (wid == 0) {
        int x = ws[lane];
        int tot = __reduce_add_sync(0xffffffffu, x);
        if (lane == 0) g_bsum[blockIdx.x] = tot;
    }
}

__global__ void scan_small_kernel() {     // 1 block, 128 threads (4 warps)
    __shared__ int ws[4];
    int t = threadIdx.x, lane = t & 31, wid = t >> 5;
    int v = (t < NBLK_SCAN) ? g_bsum[t] : 0;
    int x = warp_incl_scan(v, lane);
    if (lane == 31) ws[wid] = x;
    __syncthreads();
    int base = 0;
#pragma unroll
    for (int j = 0; j < 4; j++) base += (j < wid) ? ws[j] : 0;
    if (t < NBLK_SCAN) g_bsum[t] = base + x - v;   // exclusive
    if (t == 0) g_row_ptr[NN] = NE;
}

__global__ __launch_bounds__(1024) void scan_apply_kernel() {
    __shared__ int ws[32];
    int t = threadIdx.x, lane = t & 31, wid = t >> 5;
    int i = blockIdx.x * 1024 + t;
    int v = (i < NN) ? g_cnt_in[i] : 0;
    int x = warp_incl_scan(v, lane);
    if (lane == 31) ws[wid] = x;
    __syncthreads();
    if (wid == 0) ws[lane] = warp_incl_scan(ws[lane], lane);
    __syncthreads();
    int incl = x + (wid ? ws[wid - 1] : 0);
    if (i < NN) {
        int excl = incl - v + g_bsum[blockIdx.x];
        g_row_ptr[i] = excl;
        g_cursor[i]  = excl;
        g_norm_in[i]  = rsqrtf(fmaxf((float)v, 1.0f));
        g_norm_out[i] = rsqrtf(fmaxf((float)g_cnt_out[i], 1.0f));
    }
}

// ===========================================================================
// FUSED: gemm1 (blocks [0,GB1)) + CSR fill (blocks [GB1, GB1+FILL_BLOCKS))
// gemm1: t1[row] = half( (x[row] @ W1) * norm_out[row] )
// ===========================================================================
__global__ __launch_bounds__(256)
void fused_gemm1_fill_kernel(const float* __restrict__ X,
                             const float* __restrict__ W,
                             __half* __restrict__ Y,
                             const int* __restrict__ src,
                             const int* __restrict__ dst) {
    const int tid = threadIdx.x;
    if (blockIdx.x >= GB1) {
        int e0 = (blockIdx.x - GB1) * 256 + tid;
        for (int e = e0; e < NE; e += 256 * FILL_BLOCKS) {
            int pos = atomicAdd(&g_cursor[dst[e]], 1);
            g_csr_src[pos] = src[e];
        }
        return;
    }
    extern __shared__ float smem[];
    float* W_s = smem;                  // [128][128]
    float* x_s = W_s + 128 * 128;       // [64][128]

    for (int i = tid; i < 128 * 128 / 4; i += 256)
        ((float4*)W_s)[i] = ((const float4*)W)[i];

    const int row0 = blockIdx.x * 64;
    for (int i = tid; i < 64 * 128 / 4; i += 256) {
        int r = i >> 5, c4 = i & 31;
        int row = row0 + r;
        float4 v = (row < NN)
            ? __ldg(((const float4*)(X + (size_t)row * 128)) + c4)
            : make_float4(0.f, 0.f, 0.f, 0.f);
        ((float4*)x_s)[i] = v;
    }
    __syncthreads();

    const int ct = tid & 31;
    const int rt = tid >> 5;

    unsigned long long acc[8][2];
#pragma unroll
    for (int i = 0; i < 8; i++) { acc[i][0] = 0ULL; acc[i][1] = 0ULL; }

    for (int k = 0; k < 128; k += 4) {
        unsigned long long w[4][2];
#pragma unroll
        for (int kk = 0; kk < 4; kk++) {
            ulonglong2 wv = ((const ulonglong2*)(W_s + (k + kk) * 128))[ct];
            w[kk][0] = wv.x; w[kk][1] = wv.y;
        }
#pragma unroll
        for (int i = 0; i < 8; i++) {
            float4 xv = *((const float4*)(x_s + (rt * 8 + i) * 128 + k));
            unsigned long long xx;
            xx = dup2(xv.x);
            acc[i][0] = fma2(xx, w[0][0], acc[i][0]);
            acc[i][1] = fma2(xx, w[0][1], acc[i][1]);
            xx = dup2(xv.y);
            acc[i][0] = fma2(xx, w[1][0], acc[i][0]);
            acc[i][1] = fma2(xx, w[1][1], acc[i][1]);
            xx = dup2(xv.z);
            acc[i][0] = fma2(xx, w[2][0], acc[i][0]);
            acc[i][1] = fma2(xx, w[2][1], acc[i][1]);
            xx = dup2(xv.w);
            acc[i][0] = fma2(xx, w[3][0], acc[i][0]);
            acc[i][1] = fma2(xx, w[3][1], acc[i][1]);
        }
    }

#pragma unroll
    for (int i = 0; i < 8; i++) {
        int row = row0 + rt * 8 + i;
        if (row < NN) {
            float ns = __ldg(g_norm_out + row);
            float2 p0 = unpk(acc[i][0]), p1 = unpk(acc[i][1]);
            half4 o;
            o.a = __floats2half2_rn(p0.x * ns, p0.y * ns);
            o.b = __floats2half2_rn(p1.x * ns, p1.y * ns);
            ((half4*)(Y + (size_t)row * 128))[ct] = o;
        }
    }
}

// ===========================================================================
// FUSED layer-1-aggregate + layer-2 GEMM:
//   h[r] = relu(norm_in[r] * sum_{e} t1[csr_src[e]] + b1)   (smem only)
//   t2[r] = half( (h[r] @ W2) * norm_out[r] )
// Block: 256 threads, 64-node tile.
// ===========================================================================
__global__ __launch_bounds__(256)
void fused_gather_gemm2_kernel(const __half* __restrict__ T1,
                               const float* __restrict__ b1,
                               const float* __restrict__ W2,
                               __half* __restrict__ Y) {
    extern __shared__ float smem[];
    float* W_s = smem;                  // [128][64]  = 32KB
    float* h_s = W_s + 128 * 64;        // [64][128]  = 32KB

    const int tid  = threadIdx.x;
    const int lane = tid & 31;
    const int wid  = tid >> 5;
    const int row0 = blockIdx.x * 64;

    // W2 -> smem (independent of gather)
    for (int i = tid; i < 128 * 64 / 4; i += 256)
        ((float4*)W_s)[i] = ((const float4*)W2)[i];

    // Gather: 8 warps x 8 nodes. Each lane covers 4 feats.
    float4 bb = __ldg(((const float4*)b1) + lane);
#pragma unroll
    for (int j = 0; j < 8; j++) {
        int r = wid * 8 + j;
        int n = row0 + r;
        float4 acc = make_float4(0.f, 0.f, 0.f, 0.f);
        if (n < NN) {
            int beg = __ldg(g_row_ptr + n), end = __ldg(g_row_ptr + n + 1);
            int i = beg;
            for (; i + 1 < end; i += 2) {
                int s0 = __ldg(g_csr_src + i);
                int s1 = __ldg(g_csr_src + i + 1);
                float2 a0, c0, a1, c1;
                ldg_h4_f(T1 + (size_t)s0 * 128 + lane * 4, a0, c0);
                ldg_h4_f(T1 + (size_t)s1 * 128 + lane * 4, a1, c1);
                acc.x += a0.x + a1.x; acc.y += a0.y + a1.y;
                acc.z += c0.x + c1.x; acc.w += c0.y + c1.y;
            }
            if (i < end) {
                int s0 = __ldg(g_csr_src + i);
                float2 a0, c0;
                ldg_h4_f(T1 + (size_t)s0 * 128 + lane * 4, a0, c0);
                acc.x += a0.x; acc.y += a0.y; acc.z += c0.x; acc.w += c0.y;
            }
            float nd = __ldg(g_norm_in + n);
            acc.x = fmaxf(fmaf(acc.x, nd, bb.x), 0.f);
            acc.y = fmaxf(fmaf(acc.y, nd, bb.y), 0.f);
            acc.z = fmaxf(fmaf(acc.z, nd, bb.z), 0.f);
            acc.w = fmaxf(fmaf(acc.w, nd, bb.w), 0.f);
        }
        ((float4*)(h_s + r * 128))[lane] = acc;
    }
    __syncthreads();

    // GEMM: h_s[64][128] @ W_s[128][64] -> t2, f32x2 packed.
    const int ct = lane;       // 32 col-threads (2 cols each)
    const int rt = wid;        // 8 row-threads (8 rows each)

    unsigned long long acc2[8];
#pragma unroll
    for (int i = 0; i < 8; i++) acc2[i] = 0ULL;

    for (int k = 0; k < 128; k += 4) {
        unsigned long long w[4];
#pragma unroll
        for (int kk = 0; kk < 4; kk++)
            w[kk] = ((const unsigned long long*)(W_s + (k + kk) * 64))[ct];
#pragma unroll
        for (int i = 0; i < 8; i++) {
            float4 xv = *((const float4*)(h_s + (rt * 8 + i) * 128 + k));
            acc2[i] = fma2(dup2(xv.x), w[0], acc2[i]);
            acc2[i] = fma2(dup2(xv.y), w[1], acc2[i]);
            acc2[i] = fma2(dup2(xv.z), w[2], acc2[i]);
            acc2[i] = fma2(dup2(xv.w), w[3], acc2[i]);
        }
    }

#pragma unroll
    for (int i = 0; i < 8; i++) {
        int row = row0 + rt * 8 + i;
        if (row < NN) {
            float ns = __ldg(g_norm_out + row);
            float2 p = unpk(acc2[i]);
            ((__half2*)(Y + (size_t)row * 64))[ct] =
                __floats2half2_rn(p.x * ns, p.y * ns);
        }
    }
}

// ===========================================================================
// Final gather: out[n] = norm_in[n] * sum t2[csr_src] + b2
// ===========================================================================
__global__ __launch_bounds__(256)
void gather64_kernel(const __half* __restrict__ T,
                     const float* __restrict__ b,
                     float* __restrict__ out) {
    int w = (blockIdx.x * blockDim.x + threadIdx.x) >> 5;
    int lane = threadIdx.x & 31;
    if (w >= NN) return;
    int beg = g_row_ptr[w], end = g_row_ptr[w + 1];
    float2 acc = make_float2(0.f, 0.f);
    int i = beg;
    for (; i + 1 < end; i += 2) {
        int s0 = __ldg(g_csr_src + i);
        int s1 = __ldg(g_csr_src + i + 1);
        float2 f0 = ldg_h2_f(T + (size_t)s0 * 64 + lane * 2);
        float2 f1 = ldg_h2_f(T + (size_t)s1 * 64 + lane * 2);
        acc.x += f0.x + f1.x; acc.y += f0.y + f1.y;
    }
    if (i < end) {
        int s0 = __ldg(g_csr_src + i);
        float2 f0 = ldg_h2_f(T + (size_t)s0 * 64 + lane * 2);
        acc.x += f0.x; acc.y += f0.y;
    }
    float nd = g_norm_in[w];
    float2 bb = __ldg(((const float2*)b) + lane);
    float2 o;
    o.x = fmaf(acc.x, nd, bb.x);
    o.y = fmaf(acc.y, nd, bb.y);
    ((float2*)(out + (size_t)w * 64))[lane] = o;
}

// ===========================================================================
extern "C" void kernel_launch(void* const* d_in, const int* in_sizes, int n_in,
                              void* d_out, int out_size) {
    const float* x   = (const float*)d_in[0];
    const int*   src = (const int*)d_in[1];
    const int*   dst = (const int*)d_in[2];
    const float* W1  = (const float*)d_in[3];
    const float* b1  = (const float*)d_in[4];
    const float* W2  = (const float*)d_in[5];
    const float* b2  = (const float*)d_in[6];
    float* out = (float*)d_out;

    void *p_t1, *p_t2;
    cudaGetSymbolAddress(&p_t1, g_t1);
    cudaGetSymbolAddress(&p_t2, g_t2);

    // CSR build (fill fused with gemm1 below)
    zero_counts<<<200, 256>>>();
    count_kernel<<<(NE + 255) / 256, 256>>>(src, dst);
    block_reduce_kernel<<<NBLK_SCAN, 1024>>>();
    scan_small_kernel<<<1, 128>>>();
    scan_apply_kernel<<<NBLK_SCAN, 1024>>>();

    // Layer 1 GEMM (+ CSR fill)
    size_t sm1 = (size_t)(128 * 128 + 64 * 128) * sizeof(float);
    cudaFuncSetAttribute(fused_gemm1_fill_kernel,
                         cudaFuncAttributeMaxDynamicSharedMemorySize, (int)sm1);
    fused_gemm1_fill_kernel<<<GB1 + FILL_BLOCKS, 256, sm1>>>(
        x, W1, (__half*)p_t1, src, dst);

    // Layer 1 aggregate + Layer 2 GEMM (h never leaves smem)
    size_t sm2 = (size_t)(128 * 64 + 64 * 128) * sizeof(float);
    cudaFuncSetAttribute(fused_gather_gemm2_kernel,
                         cudaFuncAttributeMaxDynamicSharedMemorySize, (int)sm2);
    fused_gather_gemm2_kernel<<<GB1, 256, sm2>>>(
        (const __half*)p_t1, b1, W2, (__half*)p_t2);

    // Layer 2 aggregate -> output
    gather64_kernel<<<(NN * 32 + 255) / 256, 256>>>(
        (const __half*)p_t2, b2, out);
}

// round 6
// speedup vs baseline: 1.3201x; 1.3201x over previous
#include <cuda_runtime.h>
#include <cuda_fp16.h>

#define NN 100000
#define NE 1600000
#define F_HID 128
#define F_CLS 64
#define NBLK_SCAN 98               // ceil(NN/1024)
#define GB1M ((NN + 127) / 128)    // gemm1 mma tile blocks = 782
#define GB2  ((NN + 63) / 64)      // gemm2 tile blocks
#define FILL_BLOCKS 1024
#define ASTRIDE 136                // halfs per smem row (272B, LDSM conflict-free)

// ---- scratch (device globals; no allocs allowed) ----
__device__ int    g_cnt_in[NN];
__device__ int    g_cnt_out[NN];
__device__ int    g_row_ptr[NN + 1];
__device__ int    g_cursor[NN];
__device__ int    g_csr_src[NE];
__device__ float  g_norm_in[NN];
__device__ float  g_norm_out[NN];
__device__ int    g_bsum[NBLK_SCAN + 1];
__device__ __half g_t1[(size_t)NN * F_HID];
__device__ float  g_h [(size_t)NN * F_HID];
__device__ __half g_t2[(size_t)NN * F_CLS];

// ---- fp16 vector load helpers ----
__device__ __forceinline__ void ldg_h4_f(const __half* p, float2& lo, float2& hi) {
    uint2 raw = __ldg((const uint2*)p);
    lo = __half22float2(*(const __half2*)&raw.x);
    hi = __half22float2(*(const __half2*)&raw.y);
}
__device__ __forceinline__ float2 ldg_h2_f(const __half* p) {
    unsigned int raw = __ldg((const unsigned int*)p);
    return __half22float2(*(const __half2*)&raw);
}

struct alignas(8) half4 { __half2 a, b; };

// ---- f32x2 helpers (gemm2) ----
__device__ __forceinline__ unsigned long long fma2(unsigned long long a,
                                                   unsigned long long b,
                                                   unsigned long long c) {
    unsigned long long d;
    asm("fma.rn.f32x2 %0, %1, %2, %3;" : "=l"(d) : "l"(a), "l"(b), "l"(c));
    return d;
}
__device__ __forceinline__ unsigned long long dup2(float x) {
    unsigned long long d;
    unsigned int xb = __float_as_uint(x);
    asm("mov.b64 %0, {%1, %1};" : "=l"(d) : "r"(xb));
    return d;
}
__device__ __forceinline__ float2 unpk(unsigned long long v) {
    unsigned int lo, hi;
    asm("mov.b64 {%0, %1}, %2;" : "=r"(lo), "=r"(hi) : "l"(v));
    return make_float2(__uint_as_float(lo), __uint_as_float(hi));
}

__device__ __forceinline__ int warp_incl_scan(int x, int lane) {
#pragma unroll
    for (int o = 1; o < 32; o <<= 1) {
        int y = __shfl_up_sync(0xffffffffu, x, o);
        if (lane >= o) x += y;
    }
    return x;
}

// ===========================================================================
// CSR build
// ===========================================================================
__global__ __launch_bounds__(256) void count_kernel(const int4* __restrict__ src4,
                                                    const int4* __restrict__ dst4) {
    int i = blockIdx.x * blockDim.x + threadIdx.x;   // NE/4 threads
    if (i < NE / 4) {
        int4 s = __ldg(src4 + i);
        int4 d = __ldg(dst4 + i);
        atomicAdd(&g_cnt_out[s.x], 1); atomicAdd(&g_cnt_out[s.y], 1);
        atomicAdd(&g_cnt_out[s.z], 1); atomicAdd(&g_cnt_out[s.w], 1);
        atomicAdd(&g_cnt_in[d.x], 1);  atomicAdd(&g_cnt_in[d.y], 1);
        atomicAdd(&g_cnt_in[d.z], 1);  atomicAdd(&g_cnt_in[d.w], 1);
    }
}

__global__ __launch_bounds__(1024) void block_reduce_kernel() {
    __shared__ int ws[32];
    int t = threadIdx.x, lane = t & 31, wid = t >> 5;
    int i = blockIdx.x * 1024 + t;
    int v = (i < NN) ? g_cnt_in[i] : 0;
    int s = __reduce_add_sync(0xffffffffu, v);
    if (lane == 0) ws[wid] = s;
    __syncthreads();
    if (wid == 0) {
        int tot = __reduce_add_sync(0xffffffffu, ws[lane]);
        if (lane == 0) g_bsum[blockIdx.x] = tot;
    }
}

__global__ void scan_small_kernel() {     // 1 block, 128 threads
    __shared__ int ws[4];
    int t = threadIdx.x, lane = t & 31, wid = t >> 5;
    int v = (t < NBLK_SCAN) ? g_bsum[t] : 0;
    int x = warp_incl_scan(v, lane);
    if (lane == 31) ws[wid] = x;
    __syncthreads();
    int base = 0;
#pragma unroll
    for (int j = 0; j < 4; j++) base += (j < wid) ? ws[j] : 0;
    if (t < NBLK_SCAN) g_bsum[t] = base + x - v;   // exclusive
    if (t == 0) g_row_ptr[NN] = NE;
}

__global__ __launch_bounds__(1024) void scan_apply_kernel() {
    __shared__ int ws[32];
    int t = threadIdx.x, lane = t & 31, wid = t >> 5;
    int i = blockIdx.x * 1024 + t;
    int v = (i < NN) ? g_cnt_in[i] : 0;
    int x = warp_incl_scan(v, lane);
    if (lane == 31) ws[wid] = x;
    __syncthreads();
    if (wid == 0) ws[lane] = warp_incl_scan(ws[lane], lane);
    __syncthreads();
    int incl = x + (wid ? ws[wid - 1] : 0);
    if (i < NN) {
        int excl = incl - v + g_bsum[blockIdx.x];
        g_row_ptr[i] = excl;
        g_cursor[i]  = excl;
        g_norm_in[i]  = rsqrtf(fmaxf((float)v, 1.0f));
        g_norm_out[i] = rsqrtf(fmaxf((float)g_cnt_out[i], 1.0f));
    }
}

// ===========================================================================
// gemm1 (HMMA fp16, fp32 accum) + CSR fill fusion.
//   t1[row] = half( (x[row] @ W1) * norm_out[row] )
// Tile: 128 rows x 128 cols per block, 8 warps (16-row strip each), K=128.
// ===========================================================================
__global__ __launch_bounds__(256)
void fused_gemm1_fill_kernel(const float* __restrict__ X,
                             const float* __restrict__ W,
                             __half* __restrict__ Y,
                             const int* __restrict__ src,
                             const int* __restrict__ dst) {
    const int tid = threadIdx.x;
    if (blockIdx.x >= GB1M) {
        int e0 = (blockIdx.x - GB1M) * 256 + tid;
        for (int e = e0; e < NE; e += 256 * FILL_BLOCKS) {
            int pos = atomicAdd(&g_cursor[dst[e]], 1);
            g_csr_src[pos] = src[e];
        }
        return;
    }

    extern __shared__ __half hsm[];
    __half* A_s = hsm;                    // [128][ASTRIDE]
    __half* B_s = hsm + 128 * ASTRIDE;    // [128][ASTRIDE]

    const int row0 = blockIdx.x * 128;

    // W1 -> B_s fp16
    for (int i = tid; i < 128 * 32; i += 256) {
        int k = i >> 5, c4 = i & 31;
        float4 v = __ldg(((const float4*)W) + i);
        __half2 h01 = __floats2half2_rn(v.x, v.y);
        __half2 h23 = __floats2half2_rn(v.z, v.w);
        uint2 u = make_uint2(*(unsigned*)&h01, *(unsigned*)&h23);
        *((uint2*)(B_s + k * ASTRIDE + c4 * 4)) = u;
    }
    // X tile -> A_s fp16
    for (int i = tid; i < 128 * 32; i += 256) {
        int r = i >> 5, c4 = i & 31;
        int row = row0 + r;
        float4 v = (row < NN)
            ? __ldg(((const float4*)(X + (size_t)row * 128)) + c4)
            : make_float4(0.f, 0.f, 0.f, 0.f);
        __half2 h01 = __floats2half2_rn(v.x, v.y);
        __half2 h23 = __floats2half2_rn(v.z, v.w);
        uint2 u = make_uint2(*(unsigned*)&h01, *(unsigned*)&h23);
        *((uint2*)(A_s + r * ASTRIDE + c4 * 4)) = u;
    }
    __syncthreads();

    const int w = tid >> 5, lane = tid & 31;
    const int mrow = w * 16;

    float acc[16][4];
#pragma unroll
    for (int t = 0; t < 16; t++)
#pragma unroll
        for (int j = 0; j < 4; j++) acc[t][j] = 0.f;

#pragma unroll
    for (int ks = 0; ks < 8; ks++) {
        const int k0 = ks * 16;
        unsigned a0, a1, a2, a3;
        {
            const __half* pa = A_s + (mrow + (lane & 15)) * ASTRIDE
                             + k0 + (lane >> 4) * 8;
            unsigned addr = (unsigned)__cvta_generic_to_shared(pa);
            asm volatile("ldmatrix.sync.aligned.m8n8.x4.shared.b16 "
                         "{%0,%1,%2,%3}, [%4];"
                         : "=r"(a0), "=r"(a1), "=r"(a2), "=r"(a3) : "r"(addr));
        }
#pragma unroll
        for (int nt = 0; nt < 8; nt++) {
            unsigned b0, b1, b2, b3;
            const __half* pb = B_s + (k0 + (lane & 15)) * ASTRIDE
                             + nt * 16 + (lane >> 4) * 8;
            unsigned addr = (unsigned)__cvta_generic_to_shared(pb);
            asm volatile("ldmatrix.sync.aligned.m8n8.x4.trans.shared.b16 "
                         "{%0,%1,%2,%3}, [%4];"
                         : "=r"(b0), "=r"(b1), "=r"(b2), "=r"(b3) : "r"(addr));
            asm volatile("mma.sync.aligned.m16n8k16.row.col.f32.f16.f16.f32 "
                         "{%0,%1,%2,%3},{%4,%5,%6,%7},{%8,%9},{%0,%1,%2,%3};"
                         : "+f"(acc[nt*2][0]), "+f"(acc[nt*2][1]),
                           "+f"(acc[nt*2][2]), "+f"(acc[nt*2][3])
                         : "r"(a0), "r"(a1), "r"(a2), "r"(a3),
                           "r"(b0), "r"(b1));
            asm volatile("mma.sync.aligned.m16n8k16.row.col.f32.f16.f16.f32 "
                         "{%0,%1,%2,%3},{%4,%5,%6,%7},{%8,%9},{%0,%1,%2,%3};"
                         : "+f"(acc[nt*2+1][0]), "+f"(acc[nt*2+1][1]),
                           "+f"(acc[nt*2+1][2]), "+f"(acc[nt*2+1][3])
                         : "r"(a0), "r"(a1), "r"(a2), "r"(a3),
                           "r"(b2), "r"(b3));
        }
    }

    // Epilogue: c-frag lane l: rows (l>>2) and (l>>2)+8; cols n0 + (l&3)*2 +{0,1}
    const int ra = row0 + mrow + (lane >> 2);
    const int rb = ra + 8;
    const float nsa = (ra < NN) ? __ldg(g_norm_out + ra) : 0.f;
    const float nsb = (rb < NN) ? __ldg(g_norm_out + rb) : 0.f;
    const int cbase = (lane & 3) * 2;
#pragma unroll
    for (int t = 0; t < 16; t++) {
        int c = t * 8 + cbase;
        if (ra < NN) {
            __half2 h = __floats2half2_rn(acc[t][0] * nsa, acc[t][1] * nsa);
            *((__half2*)(Y + (size_t)ra * 128 + c)) = h;
        }
        if (rb < NN) {
            __half2 h = __floats2half2_rn(acc[t][2] * nsb, acc[t][3] * nsb);
            *((__half2*)(Y + (size_t)rb * 128 + c)) = h;
        }
    }
}

// ===========================================================================
// gather128+relu: h[n] = relu(norm_in[n]*sum t1[csr] + b1)   (warp/node)
// ===========================================================================
__global__ __launch_bounds__(256)
void gather128_relu_kernel(const __half* __restrict__ T,
                           const float* __restrict__ b,
                           float* __restrict__ out) {
    int w = (blockIdx.x * blockDim.x + threadIdx.x) >> 5;
    int lane = threadIdx.x & 31;
    if (w >= NN) return;
    int beg = g_row_ptr[w], end = g_row_ptr[w + 1];
    float4 acc = make_float4(0.f, 0.f, 0.f, 0.f);
    int i = beg;
    for (; i + 3 < end; i += 4) {
        int s0 = __ldg(g_csr_src + i),     s1 = __ldg(g_csr_src + i + 1);
        int s2 = __ldg(g_csr_src + i + 2), s3 = __ldg(g_csr_src + i + 3);
        float2 a0, c0, a1, c1, a2, c2, a3, c3;
        ldg_h4_f(T + (size_t)s0 * 128 + lane * 4, a0, c0);
        ldg_h4_f(T + (size_t)s1 * 128 + lane * 4, a1, c1);
        ldg_h4_f(T + (size_t)s2 * 128 + lane * 4, a2, c2);
        ldg_h4_f(T + (size_t)s3 * 128 + lane * 4, a3, c3);
        acc.x += (a0.x + a1.x) + (a2.x + a3.x);
        acc.y += (a0.y + a1.y) + (a2.y + a3.y);
        acc.z += (c0.x + c1.x) + (c2.x + c3.x);
        acc.w += (c0.y + c1.y) + (c2.y + c3.y);
    }
    for (; i < end; i++) {
        int s0 = __ldg(g_csr_src + i);
        float2 a0, c0;
        ldg_h4_f(T + (size_t)s0 * 128 + lane * 4, a0, c0);
        acc.x += a0.x; acc.y += a0.y; acc.z += c0.x; acc.w += c0.y;
    }
    float nd = g_norm_in[w];
    float4 bb = __ldg(((const float4*)b) + lane);
    float4 o;
    o.x = fmaxf(fmaf(acc.x, nd, bb.x), 0.f);
    o.y = fmaxf(fmaf(acc.y, nd, bb.y), 0.f);
    o.z = fmaxf(fmaf(acc.z, nd, bb.z), 0.f);
    o.w = fmaxf(fmaf(acc.w, nd, bb.w), 0.f);
    ((float4*)(out + (size_t)w * 128))[lane] = o;
}

// ===========================================================================
// gemm2 (SIMT f32x2): t2[row] = half( (h[row] @ W2) * norm_out[row] )
// ===========================================================================
__global__ __launch_bounds__(256)
void gemm2_kernel(const float* __restrict__ X,
                  const float* __restrict__ W,
                  __half* __restrict__ Y) {
    extern __shared__ float smem[];
    float* W_s = smem;                  // [128][64]
    float* x_s = W_s + 128 * 64;        // [64][128]

    const int tid = threadIdx.x;
    for (int i = tid; i < 128 * 64 / 4; i += 256)
        ((float4*)W_s)[i] = ((const float4*)W)[i];

    const int row0 = blockIdx.x * 64;
    for (int i = tid; i < 64 * 128 / 4; i += 256) {
        int r = i >> 5, c4 = i & 31;
        int row = row0 + r;
        float4 v = (row < NN)
            ? __ldg(((const float4*)(X + (size_t)row * 128)) + c4)
            : make_float4(0.f, 0.f, 0.f, 0.f);
        ((float4*)x_s)[i] = v;
    }
    __syncthreads();

    const int ct = tid & 31;
    const int rt = tid >> 5;

    unsigned long long acc[8];
#pragma unroll
    for (int i = 0; i < 8; i++) acc[i] = 0ULL;

    for (int k = 0; k < 128; k += 4) {
        unsigned long long w[4];
#pragma unroll
        for (int kk = 0; kk < 4; kk++)
            w[kk] = ((const unsigned long long*)(W_s + (k + kk) * 64))[ct];
#pragma unroll
        for (int i = 0; i < 8; i++) {
            float4 xv = *((const float4*)(x_s + (rt * 8 + i) * 128 + k));
            acc[i] = fma2(dup2(xv.x), w[0], acc[i]);
            acc[i] = fma2(dup2(xv.y), w[1], acc[i]);
            acc[i] = fma2(dup2(xv.z), w[2], acc[i]);
            acc[i] = fma2(dup2(xv.w), w[3], acc[i]);
        }
    }

#pragma unroll
    for (int i = 0; i < 8; i++) {
        int row = row0 + rt * 8 + i;
        if (row < NN) {
            float ns = __ldg(g_norm_out + row);
            float2 p = unpk(acc[i]);
            ((__half2*)(Y + (size_t)row * 64))[ct] =
                __floats2half2_rn(p.x * ns, p.y * ns);
        }
    }
}

// ===========================================================================
// Final gather: out[n] = norm_in[n] * sum t2[csr] + b2
// ===========================================================================
__global__ __launch_bounds__(256)
void gather64_kernel(const __half* __restrict__ T,
                     const float* __restrict__ b,
                     float* __restrict__ out) {
    int w = (blockIdx.x * blockDim.x + threadIdx.x) >> 5;
    int lane = threadIdx.x & 31;
    if (w >= NN) return;
    int beg = g_row_ptr[w], end = g_row_ptr[w + 1];
    float2 acc = make_float2(0.f, 0.f);
    int i = beg;
    for (; i + 3 < end; i += 4) {
        int s0 = __ldg(g_csr_src + i),     s1 = __ldg(g_csr_src + i + 1);
        int s2 = __ldg(g_csr_src + i + 2), s3 = __ldg(g_csr_src + i + 3);
        float2 f0 = ldg_h2_f(T + (size_t)s0 * 64 + lane * 2);
        float2 f1 = ldg_h2_f(T + (size_t)s1 * 64 + lane * 2);
        float2 f2 = ldg_h2_f(T + (size_t)s2 * 64 + lane * 2);
        float2 f3 = ldg_h2_f(T + (size_t)s3 * 64 + lane * 2);
        acc.x += (f0.x + f1.x) + (f2.x + f3.x);
        acc.y += (f0.y + f1.y) + (f2.y + f3.y);
    }
    for (; i < end; i++) {
        int s0 = __ldg(g_csr_src + i);
        float2 f0 = ldg_h2_f(T + (size_t)s0 * 64 + lane * 2);
        acc.x += f0.x; acc.y += f0.y;
    }
    float nd = g_norm_in[w];
    float2 bb = __ldg(((const float2*)b) + lane);
    float2 o;
    o.x = fmaf(acc.x, nd, bb.x);
    o.y = fmaf(acc.y, nd, bb.y);
    ((float2*)(out + (size_t)w * 64))[lane] = o;
}

// ===========================================================================
extern "C" void kernel_launch(void* const* d_in, const int* in_sizes, int n_in,
                              void* d_out, int out_size) {
    const float* x   = (const float*)d_in[0];
    const int*   src = (const int*)d_in[1];
    const int*   dst = (const int*)d_in[2];
    const float* W1  = (const float*)d_in[3];
    const float* b1  = (const float*)d_in[4];
    const float* W2  = (const float*)d_in[5];
    const float* b2  = (const float*)d_in[6];
    float* out = (float*)d_out;

    void *p_t1, *p_t2, *p_h, *p_ci, *p_co;
    cudaGetSymbolAddress(&p_t1, g_t1);
    cudaGetSymbolAddress(&p_t2, g_t2);
    cudaGetSymbolAddress(&p_h,  g_h);
    cudaGetSymbolAddress(&p_ci, g_cnt_in);
    cudaGetSymbolAddress(&p_co, g_cnt_out);

    // CSR build (fill fused with gemm1 below)
    cudaMemsetAsync(p_ci, 0, NN * sizeof(int));
    cudaMemsetAsync(p_co, 0, NN * sizeof(int));
    count_kernel<<<(NE / 4 + 255) / 256, 256>>>((const int4*)src, (const int4*)dst);
    block_reduce_kernel<<<NBLK_SCAN, 1024>>>();
    scan_small_kernel<<<1, 128>>>();
    scan_apply_kernel<<<NBLK_SCAN, 1024>>>();

    // Layer 1 GEMM (HMMA) + CSR fill
    size_t sm1 = (size_t)(2 * 128 * ASTRIDE) * sizeof(__half);   // ~68KB
    cudaFuncSetAttribute(fused_gemm1_fill_kernel,
                         cudaFuncAttributeMaxDynamicSharedMemorySize, (int)sm1);
    fused_gemm1_fill_kernel<<<GB1M + FILL_BLOCKS, 256, sm1>>>(
        x, W1, (__half*)p_t1, src, dst);

    gather128_relu_kernel<<<(NN * 32 + 255) / 256, 256>>>(
        (const __half*)p_t1, b1, (float*)p_h);

    size_t sm2 = (size_t)(128 * 64 + 64 * 128) * sizeof(float);
    cudaFuncSetAttribute(gemm2_kernel,
                         cudaFuncAttributeMaxDynamicSharedMemorySize, (int)sm2);
    gemm2_kernel<<<GB2, 256, sm2>>>((const float*)p_h, W2, (__half*)p_t2);

    gather64_kernel<<<(NN * 32 + 255) / 256, 256>>>(
        (const __half*)p_t2, b2, out);
}

// round 8
// speedup vs baseline: 1.5358x; 1.1634x over previous
#include <cuda_runtime.h>
#include <cuda_fp16.h>

#define NN 100000
#define NE 1600000
#define F_HID 128
#define F_CLS 64
#define NBLK_SCAN 98               // ceil(NN/1024)
#define GB1M ((NN + 127) / 128)    // 128-row mma tile blocks = 782
#define FILL_BLOCKS 1024
#define ASTRIDE 136                // halfs per smem row (272B, LDSM conflict-free)
#define BSTRIDE 72                 // halfs per smem row for 64-wide W2 (144B)

// ---- scratch (device globals; no allocs allowed) ----
__device__ int    g_cnt_in[NN];
__device__ int    g_cnt_out[NN];
__device__ int    g_row_ptr[NN + 1];
__device__ int    g_cursor[NN];
__device__ int    g_csr_src[NE];
__device__ float  g_norm_in[NN];
__device__ float  g_norm_out[NN];
__device__ int    g_bsum[NBLK_SCAN + 1];
__device__ __half g_t1[(size_t)NN * F_HID];
__device__ __half g_h [(size_t)NN * F_HID];   // fp16 h (layer-1 output)
__device__ __half g_t2[(size_t)NN * F_CLS];

// ---- fp16 vector load helpers ----
__device__ __forceinline__ void ldg_h4_f(const __half* p, float2& lo, float2& hi) {
    uint2 raw = __ldg((const uint2*)p);
    lo = __half22float2(*(const __half2*)&raw.x);
    hi = __half22float2(*(const __half2*)&raw.y);
}
__device__ __forceinline__ float2 ldg_h2_f(const __half* p) {
    unsigned int raw = __ldg((const unsigned int*)p);
    return __half22float2(*(const __half2*)&raw);
}

__device__ __forceinline__ int warp_incl_scan(int x, int lane) {
#pragma unroll
    for (int o = 1; o < 32; o <<= 1) {
        int y = __shfl_up_sync(0xffffffffu, x, o);
        if (lane >= o) x += y;
    }
    return x;
}

// ===========================================================================
// CSR build
// ===========================================================================
__global__ __launch_bounds__(256) void count_kernel(const int4* __restrict__ src4,
                                                    const int4* __restrict__ dst4) {
    int i = blockIdx.x * blockDim.x + threadIdx.x;   // NE/4 threads
    if (i < NE / 4) {
        int4 s = __ldg(src4 + i);
        int4 d = __ldg(dst4 + i);
        atomicAdd(&g_cnt_out[s.x], 1); atomicAdd(&g_cnt_out[s.y], 1);
        atomicAdd(&g_cnt_out[s.z], 1); atomicAdd(&g_cnt_out[s.w], 1);
        atomicAdd(&g_cnt_in[d.x], 1);  atomicAdd(&g_cnt_in[d.y], 1);
        atomicAdd(&g_cnt_in[d.z], 1);  atomicAdd(&g_cnt_in[d.w], 1);
    }
}

__global__ __launch_bounds__(1024) void block_reduce_kernel() {
    __shared__ int ws[32];
    int t = threadIdx.x, lane = t & 31, wid = t >> 5;
    int i = blockIdx.x * 1024 + t;
    int v = (i < NN) ? g_cnt_in[i] : 0;
    int s = __reduce_add_sync(0xffffffffu, v);
    if (lane == 0) ws[wid] = s;
    __syncthreads();
    if (wid == 0) {
        int tot = __reduce_add_sync(0xffffffffu, ws[lane]);
        if (lane == 0) g_bsum[blockIdx.x] = tot;
    }
}

// scan_apply with inline cross-block prefix (no separate scan_small launch)
__global__ __launch_bounds__(1024) void scan_apply_kernel() {
    __shared__ int ws[32];
    __shared__ int s_base;
    int t = threadIdx.x, lane = t & 31, wid = t >> 5;

    if (wid == 0) {   // warp 0: prefix of bsum[0..bid)
        int p = 0;
        for (int j = lane; j < (int)blockIdx.x; j += 32) p += g_bsum[j];
        p = __reduce_add_sync(0xffffffffu, p);
        if (lane == 0) s_base = p;
    }

    int i = blockIdx.x * 1024 + t;
    int v = (i < NN) ? g_cnt_in[i] : 0;
    int x = warp_incl_scan(v, lane);
    if (lane == 31) ws[wid] = x;
    __syncthreads();
    if (wid == 0) ws[lane] = warp_incl_scan(ws[lane], lane);
    __syncthreads();
    int incl = x + (wid ? ws[wid - 1] : 0);
    if (i < NN) {
        int excl = incl - v + s_base;
        g_row_ptr[i] = excl;
        g_cursor[i]  = excl;
        g_norm_in[i]  = rsqrtf(fmaxf((float)v, 1.0f));
        g_norm_out[i] = rsqrtf(fmaxf((float)g_cnt_out[i], 1.0f));
    }
    if (blockIdx.x == 0 && t == 0) g_row_ptr[NN] = NE;
}

// ===========================================================================
// gemm1 (HMMA fp16, fp32 accum) + CSR fill fusion.
//   t1[row] = half( (x[row] @ W1) * norm_out[row] )
// ===========================================================================
__global__ __launch_bounds__(256)
void fused_gemm1_fill_kernel(const float* __restrict__ X,
                             const float* __restrict__ W,
                             __half* __restrict__ Y,
                             const int* __restrict__ src,
                             const int* __restrict__ dst) {
    const int tid = threadIdx.x;
    if (blockIdx.x >= GB1M) {
        int e0 = (blockIdx.x - GB1M) * 256 + tid;
        for (int e = e0; e < NE; e += 256 * FILL_BLOCKS) {
            int pos = atomicAdd(&g_cursor[dst[e]], 1);
            g_csr_src[pos] = src[e];
        }
        return;
    }

    extern __shared__ __half hsm[];
    __half* A_s = hsm;                    // [128][ASTRIDE]
    __half* B_s = hsm + 128 * ASTRIDE;    // [128][ASTRIDE]

    const int row0 = blockIdx.x * 128;

    for (int i = tid; i < 128 * 32; i += 256) {
        int k = i >> 5, c4 = i & 31;
        float4 v = __ldg(((const float4*)W) + i);
        __half2 h01 = __floats2half2_rn(v.x, v.y);
        __half2 h23 = __floats2half2_rn(v.z, v.w);
        uint2 u = make_uint2(*(unsigned*)&h01, *(unsigned*)&h23);
        *((uint2*)(B_s + k * ASTRIDE + c4 * 4)) = u;
    }
    for (int i = tid; i < 128 * 32; i += 256) {
        int r = i >> 5, c4 = i & 31;
        int row = row0 + r;
        float4 v = (row < NN)
            ? __ldg(((const float4*)(X + (size_t)row * 128)) + c4)
            : make_float4(0.f, 0.f, 0.f, 0.f);
        __half2 h01 = __floats2half2_rn(v.x, v.y);
        __half2 h23 = __floats2half2_rn(v.z, v.w);
        uint2 u = make_uint2(*(unsigned*)&h01, *(unsigned*)&h23);
        *((uint2*)(A_s + r * ASTRIDE + c4 * 4)) = u;
    }
    __syncthreads();

    const int w = tid >> 5, lane = tid & 31;
    const int mrow = w * 16;

    float acc[16][4];
#pragma unroll
    for (int t = 0; t < 16; t++)
#pragma unroll
        for (int j = 0; j < 4; j++) acc[t][j] = 0.f;

#pragma unroll
    for (int ks = 0; ks < 8; ks++) {
        const int k0 = ks * 16;
        unsigned a0, a1, a2, a3;
        {
            const __half* pa = A_s + (mrow + (lane & 15)) * ASTRIDE
                             + k0 + (lane >> 4) * 8;
            unsigned addr = (unsigned)__cvta_generic_to_shared(pa);
            asm volatile("ldmatrix.sync.aligned.m8n8.x4.shared.b16 "
                         "{%0,%1,%2,%3}, [%4];"
                         : "=r"(a0), "=r"(a1), "=r"(a2), "=r"(a3) : "r"(addr));
        }
#pragma unroll
        for (int nt = 0; nt < 8; nt++) {
            unsigned b0, b1, b2, b3;
            const __half* pb = B_s + (k0 + (lane & 15)) * ASTRIDE
                             + nt * 16 + (lane >> 4) * 8;
            unsigned addr = (unsigned)__cvta_generic_to_shared(pb);
            asm volatile("ldmatrix.sync.aligned.m8n8.x4.trans.shared.b16 "
                         "{%0,%1,%2,%3}, [%4];"
                         : "=r"(b0), "=r"(b1), "=r"(b2), "=r"(b3) : "r"(addr));
            asm volatile("mma.sync.aligned.m16n8k16.row.col.f32.f16.f16.f32 "
                         "{%0,%1,%2,%3},{%4,%5,%6,%7},{%8,%9},{%0,%1,%2,%3};"
                         : "+f"(acc[nt*2][0]), "+f"(acc[nt*2][1]),
                           "+f"(acc[nt*2][2]), "+f"(acc[nt*2][3])
                         : "r"(a0), "r"(a1), "r"(a2), "r"(a3),
                           "r"(b0), "r"(b1));
            asm volatile("mma.sync.aligned.m16n8k16.row.col.f32.f16.f16.f32 "
                         "{%0,%1,%2,%3},{%4,%5,%6,%7},{%8,%9},{%0,%1,%2,%3};"
                         : "+f"(acc[nt*2+1][0]), "+f"(acc[nt*2+1][1]),
                           "+f"(acc[nt*2+1][2]), "+f"(acc[nt*2+1][3])
                         : "r"(a0), "r"(a1), "r"(a2), "r"(a3),
                           "r"(b2), "r"(b3));
        }
    }

    const int ra = row0 + mrow + (lane >> 2);
    const int rb = ra + 8;
    const float nsa = (ra < NN) ? __ldg(g_norm_out + ra) : 0.f;
    const float nsb = (rb < NN) ? __ldg(g_norm_out + rb) : 0.f;
    const int cbase = (lane & 3) * 2;
#pragma unroll
    for (int t = 0; t < 16; t++) {
        int c = t * 8 + cbase;
        if (ra < NN) {
            __half2 h = __floats2half2_rn(acc[t][0] * nsa, acc[t][1] * nsa);
            *((__half2*)(Y + (size_t)ra * 128 + c)) = h;
        }
        if (rb < NN) {
            __half2 h = __floats2half2_rn(acc[t][2] * nsb, acc[t][3] * nsb);
            *((__half2*)(Y + (size_t)rb * 128 + c)) = h;
        }
    }
}

// ===========================================================================
// gather128+relu: h[n] = half( relu(norm_in[n]*sum t1[csr] + b1) )
// ===========================================================================
__global__ __launch_bounds__(256)
void gather128_relu_kernel(const __half* __restrict__ T,
                           const float* __restrict__ b,
                           __half* __restrict__ out) {
    int w = (blockIdx.x * blockDim.x + threadIdx.x) >> 5;
    int lane = threadIdx.x & 31;
    if (w >= NN) return;
    int beg = g_row_ptr[w], end = g_row_ptr[w + 1];
    float4 acc = make_float4(0.f, 0.f, 0.f, 0.f);
    int i = beg;
    for (; i + 3 < end; i += 4) {
        int s0 = __ldg(g_csr_src + i),     s1 = __ldg(g_csr_src + i + 1);
        int s2 = __ldg(g_csr_src + i + 2), s3 = __ldg(g_csr_src + i + 3);
        float2 a0, c0, a1, c1, a2, c2, a3, c3;
        ldg_h4_f(T + (size_t)s0 * 128 + lane * 4, a0, c0);
        ldg_h4_f(T + (size_t)s1 * 128 + lane * 4, a1, c1);
        ldg_h4_f(T + (size_t)s2 * 128 + lane * 4, a2, c2);
        ldg_h4_f(T + (size_t)s3 * 128 + lane * 4, a3, c3);
        acc.x += (a0.x + a1.x) + (a2.x + a3.x);
        acc.y += (a0.y + a1.y) + (a2.y + a3.y);
        acc.z += (c0.x + c1.x) + (c2.x + c3.x);
        acc.w += (c0.y + c1.y) + (c2.y + c3.y);
    }
    for (; i < end; i++) {
        int s0 = __ldg(g_csr_src + i);
        float2 a0, c0;
        ldg_h4_f(T + (size_t)s0 * 128 + lane * 4, a0, c0);
        acc.x += a0.x; acc.y += a0.y; acc.z += c0.x; acc.w += c0.y;
    }
    float nd = g_norm_in[w];
    float4 bb = __ldg(((const float4*)b) + lane);
    float hx = fmaxf(fmaf(acc.x, nd, bb.x), 0.f);
    float hy = fmaxf(fmaf(acc.y, nd, bb.y), 0.f);
    float hz = fmaxf(fmaf(acc.z, nd, bb.z), 0.f);
    float hw = fmaxf(fmaf(acc.w, nd, bb.w), 0.f);
    __half2 o0 = __floats2half2_rn(hx, hy);
    __half2 o1 = __floats2half2_rn(hz, hw);
    uint2 u = make_uint2(*(unsigned*)&o0, *(unsigned*)&o1);
    ((uint2*)(out + (size_t)w * 128))[lane] = u;
}

// ===========================================================================
// gemm2 (HMMA): t2[row] = half( (h[row] @ W2) * norm_out[row] )   N=64
// Tile: 128 rows x 64 cols, 8 warps (16-row strip each), K=128.
// ===========================================================================
__global__ __launch_bounds__(256)
void gemm2_mma_kernel(const __half* __restrict__ H,
                      const float* __restrict__ W,
                      __half* __restrict__ Y) {
    extern __shared__ __half hsm[];
    __half* A_s = hsm;                    // [128][ASTRIDE]
    __half* B_s = hsm + 128 * ASTRIDE;    // [128][BSTRIDE]

    const int tid = threadIdx.x;
    const int row0 = blockIdx.x * 128;

    // W2 [128][64] fp32 -> B_s fp16  (2048 float4s)
    for (int i = tid; i < 128 * 16; i += 256) {
        int k = i >> 4, c4 = i & 15;
        float4 v = __ldg(((const float4*)W) + i);
        __half2 h01 = __floats2half2_rn(v.x, v.y);
        __half2 h23 = __floats2half2_rn(v.z, v.w);
        uint2 u = make_uint2(*(unsigned*)&h01, *(unsigned*)&h23);
        *((uint2*)(B_s + k * BSTRIDE + c4 * 4)) = u;
    }
    // h tile fp16 -> A_s: 128 rows x 128 halfs = 32 uint2 per row  (FIXED)
    for (int i = tid; i < 128 * 32; i += 256) {
        int r = i >> 5, c8 = i & 31;
        int row = row0 + r;
        uint2 u = (row < NN)
            ? __ldg(((const uint2*)(H + (size_t)row * 128)) + c8)
            : make_uint2(0u, 0u);
        *((uint2*)(A_s + r * ASTRIDE + c8 * 4)) = u;
    }
    __syncthreads();

    const int w = tid >> 5, lane = tid & 31;
    const int mrow = w * 16;

    float acc[8][4];
#pragma unroll
    for (int t = 0; t < 8; t++)
#pragma unroll
        for (int j = 0; j < 4; j++) acc[t][j] = 0.f;

#pragma unroll
    for (int ks = 0; ks < 8; ks++) {
        const int k0 = ks * 16;
        unsigned a0, a1, a2, a3;
        {
            const __half* pa = A_s + (mrow + (lane & 15)) * ASTRIDE
                             + k0 + (lane >> 4) * 8;
            unsigned addr = (unsigned)__cvta_generic_to_shared(pa);
            asm volatile("ldmatrix.sync.aligned.m8n8.x4.shared.b16 "
                         "{%0,%1,%2,%3}, [%4];"
                         : "=r"(a0), "=r"(a1), "=r"(a2), "=r"(a3) : "r"(addr));
        }
#pragma unroll
        for (int nt = 0; nt < 4; nt++) {
            unsigned b0, b1, b2, b3;
            const __half* pb = B_s + (k0 + (lane & 15)) * BSTRIDE
                             + nt * 16 + (lane >> 4) * 8;
            unsigned addr = (unsigned)__cvta_generic_to_shared(pb);
            asm volatile("ldmatrix.sync.aligned.m8n8.x4.trans.shared.b16 "
                         "{%0,%1,%2,%3}, [%4];"
                         : "=r"(b0), "=r"(b1), "=r"(b2), "=r"(b3) : "r"(addr));
            asm volatile("mma.sync.aligned.m16n8k16.row.col.f32.f16.f16.f32 "
                         "{%0,%1,%2,%3},{%4,%5,%6,%7},{%8,%9},{%0,%1,%2,%3};"
                         : "+f"(acc[nt*2][0]), "+f"(acc[nt*2][1]),
                           "+f"(acc[nt*2][2]), "+f"(acc[nt*2][3])
                         : "r"(a0), "r"(a1), "r"(a2), "r"(a3),
                           "r"(b0), "r"(b1));
            asm volatile("mma.sync.aligned.m16n8k16.row.col.f32.f16.f16.f32 "
                         "{%0,%1,%2,%3},{%4,%5,%6,%7},{%8,%9},{%0,%1,%2,%3};"
                         : "+f"(acc[nt*2+1][0]), "+f"(acc[nt*2+1][1]),
                           "+f"(acc[nt*2+1][2]), "+f"(acc[nt*2+1][3])
                         : "r"(a0), "r"(a1), "r"(a2), "r"(a3),
                           "r"(b2), "r"(b3));
        }
    }

    const int ra = row0 + mrow + (lane >> 2);
    const int rb = ra + 8;
    const float nsa = (ra < NN) ? __ldg(g_norm_out + ra) : 0.f;
    const float nsb = (rb < NN) ? __ldg(g_norm_out + rb) : 0.f;
    const int cbase = (lane & 3) * 2;
#pragma unroll
    for (int t = 0; t < 8; t++) {
        int c = t * 8 + cbase;
        if (ra < NN) {
            __half2 h = __floats2half2_rn(acc[t][0] * nsa, acc[t][1] * nsa);
            *((__half2*)(Y + (size_t)ra * 64 + c)) = h;
        }
        if (rb < NN) {
            __half2 h = __floats2half2_rn(acc[t][2] * nsb, acc[t][3] * nsb);
            *((__half2*)(Y + (size_t)rb * 64 + c)) = h;
        }
    }
}

// ===========================================================================
// Final gather: out[n] = norm_in[n] * sum t2[csr] + b2
// ===========================================================================
__global__ __launch_bounds__(256)
void gather64_kernel(const __half* __restrict__ T,
                     const float* __restrict__ b,
                     float* __restrict__ out) {
    int w = (blockIdx.x * blockDim.x + threadIdx.x) >> 5;
    int lane = threadIdx.x & 31;
    if (w >= NN) return;
    int beg = g_row_ptr[w], end = g_row_ptr[w + 1];
    float2 acc = make_float2(0.f, 0.f);
    int i = beg;
    for (; i + 3 < end; i += 4) {
        int s0 = __ldg(g_csr_src + i),     s1 = __ldg(g_csr_src + i + 1);
        int s2 = __ldg(g_csr_src + i + 2), s3 = __ldg(g_csr_src + i + 3);
        float2 f0 = ldg_h2_f(T + (size_t)s0 * 64 + lane * 2);
        float2 f1 = ldg_h2_f(T + (size_t)s1 * 64 + lane * 2);
        float2 f2 = ldg_h2_f(T + (size_t)s2 * 64 + lane * 2);
        float2 f3 = ldg_h2_f(T + (size_t)s3 * 64 + lane * 2);
        acc.x += (f0.x + f1.x) + (f2.x + f3.x);
        acc.y += (f0.y + f1.y) + (f2.y + f3.y);
    }
    for (; i < end; i++) {
        int s0 = __ldg(g_csr_src + i);
        float2 f0 = ldg_h2_f(T + (size_t)s0 * 64 + lane * 2);
        acc.x += f0.x; acc.y += f0.y;
    }
    float nd = g_norm_in[w];
    float2 bb = __ldg(((const float2*)b) + lane);
    float2 o;
    o.x = fmaf(acc.x, nd, bb.x);
    o.y = fmaf(acc.y, nd, bb.y);
    ((float2*)(out + (size_t)w * 64))[lane] = o;
}

// ===========================================================================
extern "C" void kernel_launch(void* const* d_in, const int* in_sizes, int n_in,
                              void* d_out, int out_size) {
    const float* x   = (const float*)d_in[0];
    const int*   src = (const int*)d_in[1];
    const int*   dst = (const int*)d_in[2];
    const float* W1  = (const float*)d_in[3];
    const float* b1  = (const float*)d_in[4];
    const float* W2  = (const float*)d_in[5];
    const float* b2  = (const float*)d_in[6];
    float* out = (float*)d_out;

    void *p_t1, *p_t2, *p_h, *p_ci, *p_co;
    cudaGetSymbolAddress(&p_t1, g_t1);
    cudaGetSymbolAddress(&p_t2, g_t2);
    cudaGetSymbolAddress(&p_h,  g_h);
    cudaGetSymbolAddress(&p_ci, g_cnt_in);
    cudaGetSymbolAddress(&p_co, g_cnt_out);

    cudaMemsetAsync(p_ci, 0, NN * sizeof(int));
    cudaMemsetAsync(p_co, 0, NN * sizeof(int));
    count_kernel<<<(NE / 4 + 255) / 256, 256>>>((const int4*)src, (const int4*)dst);
    block_reduce_kernel<<<NBLK_SCAN, 1024>>>();
    scan_apply_kernel<<<NBLK_SCAN, 1024>>>();

    size_t sm1 = (size_t)(2 * 128 * ASTRIDE) * sizeof(__half);   // ~68KB
    cudaFuncSetAttribute(fused_gemm1_fill_kernel,
                         cudaFuncAttributeMaxDynamicSharedMemorySize, (int)sm1);
    fused_gemm1_fill_kernel<<<GB1M + FILL_BLOCKS, 256, sm1>>>(
        x, W1, (__half*)p_t1, src, dst);

    gather128_relu_kernel<<<(NN * 32 + 255) / 256, 256>>>(
        (const __half*)p_t1, b1, (__half*)p_h);

    size_t sm2 = (size_t)(128 * ASTRIDE + 128 * BSTRIDE) * sizeof(__half);
    cudaFuncSetAttribute(gemm2_mma_kernel,
                         cudaFuncAttributeMaxDynamicSharedMemorySize, (int)sm2);
    gemm2_mma_kernel<<<GB1M, 256, sm2>>>(
        (const __half*)p_h, W2, (__half*)p_t2);

    gather64_kernel<<<(NN * 32 + 255) / 256, 256>>>(
        (const __half*)p_t2, b2, out);
}

// round 9
// speedup vs baseline: 1.5755x; 1.0258x over previous
#include <cuda_runtime.h>
#include <cuda_fp16.h>

#define NN 100000
#define NE 1600000
#define F_HID 128
#define F_CLS 64
#define NBLK_SCAN 98               // ceil(NN/1024)
#define GB1M ((NN + 127) / 128)    // 128-row mma tile blocks = 782
#define ASTRIDE 136                // halfs per smem row (272B, LDSM conflict-free)
#define BSTRIDE 72                 // halfs per smem row for 64-wide W2 (144B)

// ---- scratch (device globals; no allocs allowed) ----
__device__ int    g_cnt_in[NN];
__device__ int    g_cnt_out[NN];
__device__ int    g_row_ptr[NN + 1];
__device__ int    g_epos[NE];       // edge position within its dst row
__device__ int    g_csr_src[NE];
__device__ float  g_norm_in[NN];
__device__ float  g_norm_out[NN];
__device__ int    g_bsum[NBLK_SCAN + 1];
__device__ __half g_t1[(size_t)NN * F_HID];
__device__ __half g_h [(size_t)NN * F_HID];
__device__ __half g_t2[(size_t)NN * F_CLS];

// ---- fp16 vector load helpers ----
__device__ __forceinline__ void ldg_h4_f(const __half* p, float2& lo, float2& hi) {
    uint2 raw = __ldg((const uint2*)p);
    lo = __half22float2(*(const __half2*)&raw.x);
    hi = __half22float2(*(const __half2*)&raw.y);
}
__device__ __forceinline__ float2 ldg_h2_f(const __half* p) {
    unsigned int raw = __ldg((const unsigned int*)p);
    return __half22float2(*(const __half2*)&raw);
}

__device__ __forceinline__ int warp_incl_scan(int x, int lane) {
#pragma unroll
    for (int o = 1; o < 32; o <<= 1) {
        int y = __shfl_up_sync(0xffffffffu, x, o);
        if (lane >= o) x += y;
    }
    return x;
}

// ===========================================================================
// CSR build
// ===========================================================================
// count: in-degree/out-degree; atomic return value = edge position in row.
__global__ __launch_bounds__(256) void count_kernel(const int4* __restrict__ src4,
                                                    const int4* __restrict__ dst4) {
    int i = blockIdx.x * blockDim.x + threadIdx.x;   // NE/4 threads
    if (i < NE / 4) {
        int4 s = __ldg(src4 + i);
        int4 d = __ldg(dst4 + i);
        atomicAdd(&g_cnt_out[s.x], 1); atomicAdd(&g_cnt_out[s.y], 1);
        atomicAdd(&g_cnt_out[s.z], 1); atomicAdd(&g_cnt_out[s.w], 1);
        int4 p;
        p.x = atomicAdd(&g_cnt_in[d.x], 1);
        p.y = atomicAdd(&g_cnt_in[d.y], 1);
        p.z = atomicAdd(&g_cnt_in[d.z], 1);
        p.w = atomicAdd(&g_cnt_in[d.w], 1);
        ((int4*)g_epos)[i] = p;
    }
}

__global__ __launch_bounds__(1024) void block_reduce_kernel() {
    __shared__ int ws[32];
    int t = threadIdx.x, lane = t & 31, wid = t >> 5;
    int i = blockIdx.x * 1024 + t;
    int v = (i < NN) ? g_cnt_in[i] : 0;
    int s = __reduce_add_sync(0xffffffffu, v);
    if (lane == 0) ws[wid] = s;
    __syncthreads();
    if (wid == 0) {
        int tot = __reduce_add_sync(0xffffffffu, ws[lane]);
        if (lane == 0) g_bsum[blockIdx.x] = tot;
    }
}

// scan_apply with inline cross-block prefix
__global__ __launch_bounds__(1024) void scan_apply_kernel() {
    __shared__ int ws[32];
    __shared__ int s_base;
    int t = threadIdx.x, lane = t & 31, wid = t >> 5;

    if (wid == 0) {   // warp 0: prefix of bsum[0..bid)
        int p = 0;
        for (int j = lane; j < (int)blockIdx.x; j += 32) p += g_bsum[j];
        p = __reduce_add_sync(0xffffffffu, p);
        if (lane == 0) s_base = p;
    }

    int i = blockIdx.x * 1024 + t;
    int v = (i < NN) ? g_cnt_in[i] : 0;
    int x = warp_incl_scan(v, lane);
    if (lane == 31) ws[wid] = x;
    __syncthreads();
    if (wid == 0) ws[lane] = warp_incl_scan(ws[lane], lane);
    __syncthreads();
    int incl = x + (wid ? ws[wid - 1] : 0);
    if (i < NN) {
        g_row_ptr[i] = incl - v + s_base;
        g_norm_in[i]  = rsqrtf(fmaxf((float)v, 1.0f));
        g_norm_out[i] = rsqrtf(fmaxf((float)g_cnt_out[i], 1.0f));
    }
    if (blockIdx.x == 0 && t == 0) g_row_ptr[NN] = NE;
}

// fill: pure scatter, no atomics, no smem -> full occupancy.
__global__ __launch_bounds__(256) void fill_kernel(const int4* __restrict__ src4,
                                                   const int4* __restrict__ dst4) {
    int i = blockIdx.x * blockDim.x + threadIdx.x;
    if (i < NE / 4) {
        int4 s = __ldg(src4 + i);
        int4 d = __ldg(dst4 + i);
        int4 p = ((const int4*)g_epos)[i];
        g_csr_src[__ldg(g_row_ptr + d.x) + p.x] = s.x;
        g_csr_src[__ldg(g_row_ptr + d.y) + p.y] = s.y;
        g_csr_src[__ldg(g_row_ptr + d.z) + p.z] = s.z;
        g_csr_src[__ldg(g_row_ptr + d.w) + p.w] = s.w;
    }
}

// ===========================================================================
// gemm1 (HMMA fp16, fp32 accum):
//   t1[row] = half( (x[row] @ W1) * norm_out[row] )
// ===========================================================================
__global__ __launch_bounds__(256)
void gemm1_mma_kernel(const float* __restrict__ X,
                      const float* __restrict__ W,
                      __half* __restrict__ Y) {
    extern __shared__ __half hsm[];
    __half* A_s = hsm;                    // [128][ASTRIDE]
    __half* B_s = hsm + 128 * ASTRIDE;    // [128][ASTRIDE]

    const int tid = threadIdx.x;
    const int row0 = blockIdx.x * 128;

    for (int i = tid; i < 128 * 32; i += 256) {
        int k = i >> 5, c4 = i & 31;
        float4 v = __ldg(((const float4*)W) + i);
        __half2 h01 = __floats2half2_rn(v.x, v.y);
        __half2 h23 = __floats2half2_rn(v.z, v.w);
        uint2 u = make_uint2(*(unsigned*)&h01, *(unsigned*)&h23);
        *((uint2*)(B_s + k * ASTRIDE + c4 * 4)) = u;
    }
    for (int i = tid; i < 128 * 32; i += 256) {
        int r = i >> 5, c4 = i & 31;
        int row = row0 + r;
        float4 v = (row < NN)
            ? __ldg(((const float4*)(X + (size_t)row * 128)) + c4)
            : make_float4(0.f, 0.f, 0.f, 0.f);
        __half2 h01 = __floats2half2_rn(v.x, v.y);
        __half2 h23 = __floats2half2_rn(v.z, v.w);
        uint2 u = make_uint2(*(unsigned*)&h01, *(unsigned*)&h23);
        *((uint2*)(A_s + r * ASTRIDE + c4 * 4)) = u;
    }
    __syncthreads();

    const int w = tid >> 5, lane = tid & 31;
    const int mrow = w * 16;

    float acc[16][4];
#pragma unroll
    for (int t = 0; t < 16; t++)
#pragma unroll
        for (int j = 0; j < 4; j++) acc[t][j] = 0.f;

#pragma unroll
    for (int ks = 0; ks < 8; ks++) {
        const int k0 = ks * 16;
        unsigned a0, a1, a2, a3;
        {
            const __half* pa = A_s + (mrow + (lane & 15)) * ASTRIDE
                             + k0 + (lane >> 4) * 8;
            unsigned addr = (unsigned)__cvta_generic_to_shared(pa);
            asm volatile("ldmatrix.sync.aligned.m8n8.x4.shared.b16 "
                         "{%0,%1,%2,%3}, [%4];"
                         : "=r"(a0), "=r"(a1), "=r"(a2), "=r"(a3) : "r"(addr));
        }
#pragma unroll
        for (int nt = 0; nt < 8; nt++) {
            unsigned b0, b1, b2, b3;
            const __half* pb = B_s + (k0 + (lane & 15)) * ASTRIDE
                             + nt * 16 + (lane >> 4) * 8;
            unsigned addr = (unsigned)__cvta_generic_to_shared(pb);
            asm volatile("ldmatrix.sync.aligned.m8n8.x4.trans.shared.b16 "
                         "{%0,%1,%2,%3}, [%4];"
                         : "=r"(b0), "=r"(b1), "=r"(b2), "=r"(b3) : "r"(addr));
            asm volatile("mma.sync.aligned.m16n8k16.row.col.f32.f16.f16.f32 "
                         "{%0,%1,%2,%3},{%4,%5,%6,%7},{%8,%9},{%0,%1,%2,%3};"
                         : "+f"(acc[nt*2][0]), "+f"(acc[nt*2][1]),
                           "+f"(acc[nt*2][2]), "+f"(acc[nt*2][3])
                         : "r"(a0), "r"(a1), "r"(a2), "r"(a3),
                           "r"(b0), "r"(b1));
            asm volatile("mma.sync.aligned.m16n8k16.row.col.f32.f16.f16.f32 "
                         "{%0,%1,%2,%3},{%4,%5,%6,%7},{%8,%9},{%0,%1,%2,%3};"
                         : "+f"(acc[nt*2+1][0]), "+f"(acc[nt*2+1][1]),
                           "+f"(acc[nt*2+1][2]), "+f"(acc[nt*2+1][3])
                         : "r"(a0), "r"(a1), "r"(a2), "r"(a3),
                           "r"(b2), "r"(b3));
        }
    }

    const int ra = row0 + mrow + (lane >> 2);
    const int rb = ra + 8;
    const float nsa = (ra < NN) ? __ldg(g_norm_out + ra) : 0.f;
    const float nsb = (rb < NN) ? __ldg(g_norm_out + rb) : 0.f;
    const int cbase = (lane & 3) * 2;
#pragma unroll
    for (int t = 0; t < 16; t++) {
        int c = t * 8 + cbase;
        if (ra < NN) {
            __half2 h = __floats2half2_rn(acc[t][0] * nsa, acc[t][1] * nsa);
            *((__half2*)(Y + (size_t)ra * 128 + c)) = h;
        }
        if (rb < NN) {
            __half2 h = __floats2half2_rn(acc[t][2] * nsb, acc[t][3] * nsb);
            *((__half2*)(Y + (size_t)rb * 128 + c)) = h;
        }
    }
}

// ===========================================================================
// gather128+relu: h[n] = half( relu(norm_in[n]*sum t1[csr] + b1) )
// ===========================================================================
__global__ __launch_bounds__(256)
void gather128_relu_kernel(const __half* __restrict__ T,
                           const float* __restrict__ b,
                           __half* __restrict__ out) {
    int w = (blockIdx.x * blockDim.x + threadIdx.x) >> 5;
    int lane = threadIdx.x & 31;
    if (w >= NN) return;
    int beg = g_row_ptr[w], end = g_row_ptr[w + 1];
    float4 acc = make_float4(0.f, 0.f, 0.f, 0.f);
    int i = beg;
    for (; i + 3 < end; i += 4) {
        int s0 = __ldg(g_csr_src + i),     s1 = __ldg(g_csr_src + i + 1);
        int s2 = __ldg(g_csr_src + i + 2), s3 = __ldg(g_csr_src + i + 3);
        float2 a0, c0, a1, c1, a2, c2, a3, c3;
        ldg_h4_f(T + (size_t)s0 * 128 + lane * 4, a0, c0);
        ldg_h4_f(T + (size_t)s1 * 128 + lane * 4, a1, c1);
        ldg_h4_f(T + (size_t)s2 * 128 + lane * 4, a2, c2);
        ldg_h4_f(T + (size_t)s3 * 128 + lane * 4, a3, c3);
        acc.x += (a0.x + a1.x) + (a2.x + a3.x);
        acc.y += (a0.y + a1.y) + (a2.y + a3.y);
        acc.z += (c0.x + c1.x) + (c2.x + c3.x);
        acc.w += (c0.y + c1.y) + (c2.y + c3.y);
    }
    for (; i < end; i++) {
        int s0 = __ldg(g_csr_src + i);
        float2 a0, c0;
        ldg_h4_f(T + (size_t)s0 * 128 + lane * 4, a0, c0);
        acc.x += a0.x; acc.y += a0.y; acc.z += c0.x; acc.w += c0.y;
    }
    float nd = g_norm_in[w];
    float4 bb = __ldg(((const float4*)b) + lane);
    float hx = fmaxf(fmaf(acc.x, nd, bb.x), 0.f);
    float hy = fmaxf(fmaf(acc.y, nd, bb.y), 0.f);
    float hz = fmaxf(fmaf(acc.z, nd, bb.z), 0.f);
    float hw = fmaxf(fmaf(acc.w, nd, bb.w), 0.f);
    __half2 o0 = __floats2half2_rn(hx, hy);
    __half2 o1 = __floats2half2_rn(hz, hw);
    uint2 u = make_uint2(*(unsigned*)&o0, *(unsigned*)&o1);
    ((uint2*)(out + (size_t)w * 128))[lane] = u;
}

// ===========================================================================
// gemm2 (HMMA): t2[row] = half( (h[row] @ W2) * norm_out[row] )   N=64
// ===========================================================================
__global__ __launch_bounds__(256)
void gemm2_mma_kernel(const __half* __restrict__ H,
                      const float* __restrict__ W,
                      __half* __restrict__ Y) {
    extern __shared__ __half hsm[];
    __half* A_s = hsm;                    // [128][ASTRIDE]
    __half* B_s = hsm + 128 * ASTRIDE;    // [128][BSTRIDE]

    const int tid = threadIdx.x;
    const int row0 = blockIdx.x * 128;

    for (int i = tid; i < 128 * 16; i += 256) {
        int k = i >> 4, c4 = i & 15;
        float4 v = __ldg(((const float4*)W) + i);
        __half2 h01 = __floats2half2_rn(v.x, v.y);
        __half2 h23 = __floats2half2_rn(v.z, v.w);
        uint2 u = make_uint2(*(unsigned*)&h01, *(unsigned*)&h23);
        *((uint2*)(B_s + k * BSTRIDE + c4 * 4)) = u;
    }
    for (int i = tid; i < 128 * 32; i += 256) {
        int r = i >> 5, c8 = i & 31;
        int row = row0 + r;
        uint2 u = (row < NN)
            ? __ldg(((const uint2*)(H + (size_t)row * 128)) + c8)
            : make_uint2(0u, 0u);
        *((uint2*)(A_s + r * ASTRIDE + c8 * 4)) = u;
    }
    __syncthreads();

    const int w = tid >> 5, lane = tid & 31;
    const int mrow = w * 16;

    float acc[8][4];
#pragma unroll
    for (int t = 0; t < 8; t++)
#pragma unroll
        for (int j = 0; j < 4; j++) acc[t][j] = 0.f;

#pragma unroll
    for (int ks = 0; ks < 8; ks++) {
        const int k0 = ks * 16;
        unsigned a0, a1, a2, a3;
        {
            const __half* pa = A_s + (mrow + (lane & 15)) * ASTRIDE
                             + k0 + (lane >> 4) * 8;
            unsigned addr = (unsigned)__cvta_generic_to_shared(pa);
            asm volatile("ldmatrix.sync.aligned.m8n8.x4.shared.b16 "
                         "{%0,%1,%2,%3}, [%4];"
                         : "=r"(a0), "=r"(a1), "=r"(a2), "=r"(a3) : "r"(addr));
        }
#pragma unroll
        for (int nt = 0; nt < 4; nt++) {
            unsigned b0, b1, b2, b3;
            const __half* pb = B_s + (k0 + (lane & 15)) * BSTRIDE
                             + nt * 16 + (lane >> 4) * 8;
            unsigned addr = (unsigned)__cvta_generic_to_shared(pb);
            asm volatile("ldmatrix.sync.aligned.m8n8.x4.trans.shared.b16 "
                         "{%0,%1,%2,%3}, [%4];"
                         : "=r"(b0), "=r"(b1), "=r"(b2), "=r"(b3) : "r"(addr));
            asm volatile("mma.sync.aligned.m16n8k16.row.col.f32.f16.f16.f32 "
                         "{%0,%1,%2,%3},{%4,%5,%6,%7},{%8,%9},{%0,%1,%2,%3};"
                         : "+f"(acc[nt*2][0]), "+f"(acc[nt*2][1]),
                           "+f"(acc[nt*2][2]), "+f"(acc[nt*2][3])
                         : "r"(a0), "r"(a1), "r"(a2), "r"(a3),
                           "r"(b0), "r"(b1));
            asm volatile("mma.sync.aligned.m16n8k16.row.col.f32.f16.f16.f32 "
                         "{%0,%1,%2,%3},{%4,%5,%6,%7},{%8,%9},{%0,%1,%2,%3};"
                         : "+f"(acc[nt*2+1][0]), "+f"(acc[nt*2+1][1]),
                           "+f"(acc[nt*2+1][2]), "+f"(acc[nt*2+1][3])
                         : "r"(a0), "r"(a1), "r"(a2), "r"(a3),
                           "r"(b2), "r"(b3));
        }
    }

    const int ra = row0 + mrow + (lane >> 2);
    const int rb = ra + 8;
    const float nsa = (ra < NN) ? __ldg(g_norm_out + ra) : 0.f;
    const float nsb = (rb < NN) ? __ldg(g_norm_out + rb) : 0.f;
    const int cbase = (lane & 3) * 2;
#pragma unroll
    for (int t = 0; t < 8; t++) {
        int c = t * 8 + cbase;
        if (ra < NN) {
            __half2 h = __floats2half2_rn(acc[t][0] * nsa, acc[t][1] * nsa);
            *((__half2*)(Y + (size_t)ra * 64 + c)) = h;
        }
        if (rb < NN) {
            __half2 h = __floats2half2_rn(acc[t][2] * nsb, acc[t][3] * nsb);
            *((__half2*)(Y + (size_t)rb * 64 + c)) = h;
        }
    }
}

// ===========================================================================
// Final gather: out[n] = norm_in[n] * sum t2[csr] + b2
// ===========================================================================
__global__ __launch_bounds__(256)
void gather64_kernel(const __half* __restrict__ T,
                     const float* __restrict__ b,
                     float* __restrict__ out) {
    int w = (blockIdx.x * blockDim.x + threadIdx.x) >> 5;
    int lane = threadIdx.x & 31;
    if (w >= NN) return;
    int beg = g_row_ptr[w], end = g_row_ptr[w + 1];
    float2 acc = make_float2(0.f, 0.f);
    int i = beg;
    for (; i + 3 < end; i += 4) {
        int s0 = __ldg(g_csr_src + i),     s1 = __ldg(g_csr_src + i + 1);
        int s2 = __ldg(g_csr_src + i + 2), s3 = __ldg(g_csr_src + i + 3);
        float2 f0 = ldg_h2_f(T + (size_t)s0 * 64 + lane * 2);
        float2 f1 = ldg_h2_f(T + (size_t)s1 * 64 + lane * 2);
        float2 f2 = ldg_h2_f(T + (size_t)s2 * 64 + lane * 2);
        float2 f3 = ldg_h2_f(T + (size_t)s3 * 64 + lane * 2);
        acc.x += (f0.x + f1.x) + (f2.x + f3.x);
        acc.y += (f0.y + f1.y) + (f2.y + f3.y);
    }
    for (; i < end; i++) {
        int s0 = __ldg(g_csr_src + i);
        float2 f0 = ldg_h2_f(T + (size_t)s0 * 64 + lane * 2);
        acc.x += f0.x; acc.y += f0.y;
    }
    float nd = g_norm_in[w];
    float2 bb = __ldg(((const float2*)b) + lane);
    float2 o;
    o.x = fmaf(acc.x, nd, bb.x);
    o.y = fmaf(acc.y, nd, bb.y);
    ((float2*)(out + (size_t)w * 64))[lane] = o;
}

// ===========================================================================
extern "C" void kernel_launch(void* const* d_in, const int* in_sizes, int n_in,
                              void* d_out, int out_size) {
    const float* x   = (const float*)d_in[0];
    const int*   src = (const int*)d_in[1];
    const int*   dst = (const int*)d_in[2];
    const float* W1  = (const float*)d_in[3];
    const float* b1  = (const float*)d_in[4];
    const float* W2  = (const float*)d_in[5];
    const float* b2  = (const float*)d_in[6];
    float* out = (float*)d_out;

    void *p_t1, *p_t2, *p_h, *p_ci, *p_co;
    cudaGetSymbolAddress(&p_t1, g_t1);
    cudaGetSymbolAddress(&p_t2, g_t2);
    cudaGetSymbolAddress(&p_h,  g_h);
    cudaGetSymbolAddress(&p_ci, g_cnt_in);
    cudaGetSymbolAddress(&p_co, g_cnt_out);

    cudaMemsetAsync(p_ci, 0, NN * sizeof(int));
    cudaMemsetAsync(p_co, 0, NN * sizeof(int));
    count_kernel<<<(NE / 4 + 255) / 256, 256>>>((const int4*)src, (const int4*)dst);
    block_reduce_kernel<<<NBLK_SCAN, 1024>>>();
    scan_apply_kernel<<<NBLK_SCAN, 1024>>>();
    fill_kernel<<<(NE / 4 + 255) / 256, 256>>>((const int4*)src, (const int4*)dst);

    size_t sm1 = (size_t)(2 * 128 * ASTRIDE) * sizeof(__half);   // ~68KB
    cudaFuncSetAttribute(gemm1_mma_kernel,
                         cudaFuncAttributeMaxDynamicSharedMemorySize, (int)sm1);
    gemm1_mma_kernel<<<GB1M, 256, sm1>>>(x, W1, (__half*)p_t1);

    gather128_relu_kernel<<<(NN * 32 + 255) / 256, 256>>>(
        (const __half*)p_t1, b1, (__half*)p_h);

    size_t sm2 = (size_t)(128 * ASTRIDE + 128 * BSTRIDE) * sizeof(__half);
    cudaFuncSetAttribute(gemm2_mma_kernel,
                         cudaFuncAttributeMaxDynamicSharedMemorySize, (int)sm2);
    gemm2_mma_kernel<<<GB1M, 256, sm2>>>(
        (const __half*)p_h, W2, (__half*)p_t2);

    gather64_kernel<<<(NN * 32 + 255) / 256, 256>>>(
        (const __half*)p_t2, b2, out);
}